// round 5
// baseline (speedup 1.0000x reference)
#include <cuda_runtime.h>

// ---------------------------------------------------------------------------
// MSGMS loss, 4-scale pyramid, fused median3+Prewitt+GMS per scale.
// Key identities used:
//   * channel-mean commutes with avg_pool2 -> pool grayscale only
//   * gmap needs only sqrt(sI*sR) where s = gx^2+gy^2
//   * median-of-9 via sorted columns: 3-sort + (max3, med3, min3, med3)
// ---------------------------------------------------------------------------

#define C_GMS 0.0026f

static constexpr int NB   = 16;
static constexpr int OFF0 = 0;
static constexpr int OFF1 = OFF0 + 16 * 512 * 512;
static constexpr int OFF2 = OFF1 + 16 * 256 * 256;
static constexpr int OFF3 = OFF2 + 16 * 128 * 128;
static constexpr int GTOT = OFF3 + 16 * 64 * 64;

__device__ float  g_grayI[GTOT];
__device__ float  g_grayR[GTOT];
__device__ double g_accum;

__global__ void zero_accum_k() { g_accum = 0.0; }

__global__ void finalize_k(float* __restrict__ out) { out[0] = (float)g_accum; }

// ---------------------------------------------------------------------------
// Grayscale: gray = (c0+c1+c2)/3 for both images at scale 0 (512x512).
// float4-vectorized; 6 loads + 2 stores per thread.
// ---------------------------------------------------------------------------
__global__ void gray_k(const float* __restrict__ Ii, const float* __restrict__ Ir) {
    constexpr int HW = 512 * 512;
    constexpr int Q  = HW / 4;
    int i4 = blockIdx.x * blockDim.x + threadIdx.x;
    if (i4 >= NB * Q) return;
    int b = i4 / Q, p = i4 % Q;
    const float inv3 = 1.0f / 3.0f;
    {
        const float4* s = (const float4*)Ii + (size_t)b * 3 * Q;
        float4 c0 = s[p], c1 = s[Q + p], c2 = s[2 * Q + p];
        float4 o = { (c0.x + c1.x + c2.x) * inv3, (c0.y + c1.y + c2.y) * inv3,
                     (c0.z + c1.z + c2.z) * inv3, (c0.w + c1.w + c2.w) * inv3 };
        ((float4*)g_grayI)[(size_t)b * Q + p] = o;
    }
    {
        const float4* s = (const float4*)Ir + (size_t)b * 3 * Q;
        float4 c0 = s[p], c1 = s[Q + p], c2 = s[2 * Q + p];
        float4 o = { (c0.x + c1.x + c2.x) * inv3, (c0.y + c1.y + c2.y) * inv3,
                     (c0.z + c1.z + c2.z) * inv3, (c0.w + c1.w + c2.w) * inv3 };
        ((float4*)g_grayR)[(size_t)b * Q + p] = o;
    }
}

// ---------------------------------------------------------------------------
// 2x2 avg-pool on grayscale, both images. One thread -> 2 output pixels
// (float4 in per row, float2 out).
// ---------------------------------------------------------------------------
__global__ void pool_k(int Hin, int Win, int offIn, int offOut) {
    int Hout = Hin >> 1, Wout = Win >> 1;
    int W2 = Wout >> 1;                       // out-pixel pairs per row
    int per_img = NB * Hout * W2;
    int idx = blockIdx.x * blockDim.x + threadIdx.x;
    if (idx >= 2 * per_img) return;
    float* buf = (idx >= per_img) ? g_grayR : g_grayI;
    if (idx >= per_img) idx -= per_img;
    int b   = idx / (Hout * W2);
    int rem = idx % (Hout * W2);
    int oy  = rem / W2;
    int k   = rem % W2;
    const float4* r0 = (const float4*)(buf + offIn + (size_t)b * Hin * Win + (size_t)(2 * oy) * Win) + k;
    const float4* r1 = r0 + (Win >> 2);
    float4 f = *r0, g = *r1;
    float2 o;
    o.x = (f.x + f.y + g.x + g.y) * 0.25f;
    o.y = (f.z + f.w + g.z + g.w) * 0.25f;
    ((float2*)(buf + offOut + (size_t)b * Hout * Wout + (size_t)oy * Wout))[k] = o;
}

// ---------------------------------------------------------------------------
// Fused GMS kernel for one scale.
// Block: 32x8 threads, 32x32 output tile.
//  Stage A: sorted vertical triples S(r,c): 34 median-rows x 36 gray-cols x 2 imgs
//  Stage B: median tile 34x34 x 2 imgs from 3 adjacent sorted columns
//  Stage C: Prewitt + gmap + block reduction -> atomicAdd(double)
// ---------------------------------------------------------------------------
__device__ __forceinline__ float med3f(float a, float b, float c) {
    return fmaxf(fminf(a, b), fminf(fmaxf(a, b), c));
}
__device__ __forceinline__ void sort3f(float& a, float& b, float& c) {
    float t;
    t = fminf(a, b); b = fmaxf(a, b); a = t;
    t = fminf(b, c); c = fmaxf(b, c); b = t;
    t = fminf(a, b); b = fmaxf(a, b); a = t;
}
__device__ __forceinline__ float ld0(const float* __restrict__ g, int y, int x, int H, int W) {
    return ((unsigned)y < (unsigned)H && (unsigned)x < (unsigned)W) ? __ldg(g + (size_t)y * W + x) : 0.0f;
}

__global__ __launch_bounds__(256) void gms_k(int H, int W, int off, float weight) {
    const int OX = blockIdx.x * 32;
    const int OY = blockIdx.y * 32;
    const int b  = blockIdx.z;
    const int tid = threadIdx.y * 32 + threadIdx.x;

    __shared__ float sLo[2][34][36];
    __shared__ float sMi[2][34][36];
    __shared__ float sHi[2][34][36];
    __shared__ float sMed[2][34][36];   // only cols [0,34) used

    const float* __restrict__ gI = g_grayI + off + (size_t)b * H * W;
    const float* __restrict__ gR = g_grayR + off + (size_t)b * H * W;

    // ---- Stage A: sorted vertical triples (zero-padded borders) ----
    for (int t = tid; t < 2 * 34 * 36; t += 256) {
        int img = t / (34 * 36);
        int rem = t % (34 * 36);
        int r = rem / 36, c = rem % 36;
        int my = OY + r;          // median row
        int gx = OX - 1 + c;      // gray col
        const float* g = img ? gR : gI;
        float v0 = ld0(g, my - 1, gx, H, W);
        float v1 = ld0(g, my,     gx, H, W);
        float v2 = ld0(g, my + 1, gx, H, W);
        sort3f(v0, v1, v2);
        sLo[img][r][c] = v0;
        sMi[img][r][c] = v1;
        sHi[img][r][c] = v2;
    }
    __syncthreads();

    // ---- Stage B: median of 9 from 3 sorted columns ----
    for (int t = tid; t < 2 * 34 * 34; t += 256) {
        int img = t / (34 * 34);
        int rem = t % (34 * 34);
        int r = rem / 34, m = rem % 34;
        float lo = fmaxf(fmaxf(sLo[img][r][m], sLo[img][r][m + 1]), sLo[img][r][m + 2]);
        float mi = med3f(sMi[img][r][m], sMi[img][r][m + 1], sMi[img][r][m + 2]);
        float hi = fminf(fminf(sHi[img][r][m], sHi[img][r][m + 1]), sHi[img][r][m + 2]);
        sMed[img][r][m] = med3f(lo, mi, hi);
    }
    __syncthreads();

    // ---- Stage C: Prewitt + GMS map + accumulate ----
    const float inv3 = 1.0f / 3.0f;
    float acc = 0.0f;
    const int Hm2 = H - 2, Wm2 = W - 2;
#pragma unroll
    for (int v = 0; v < 4; v++) {
        int ry = threadIdx.y + 8 * v;         // local output row 0..31
        int oy = OY + ry;
        int ox = OX + threadIdx.x;
        if (oy < Hm2 && ox < Wm2) {
            int m = threadIdx.x;
            // image I
            float a00 = sMed[0][ry][m],     a01 = sMed[0][ry][m + 1],     a02 = sMed[0][ry][m + 2];
            float a10 = sMed[0][ry + 1][m],                               a12 = sMed[0][ry + 1][m + 2];
            float a20 = sMed[0][ry + 2][m], a21 = sMed[0][ry + 2][m + 1], a22 = sMed[0][ry + 2][m + 2];
            float gxI = (a02 + a12 + a22 - a00 - a10 - a20) * inv3;
            float gyI = (a00 + a01 + a02 - a20 - a21 - a22) * inv3;
            float sI  = gxI * gxI + gyI * gyI;
            // image R
            float b00 = sMed[1][ry][m],     b01 = sMed[1][ry][m + 1],     b02 = sMed[1][ry][m + 2];
            float b10 = sMed[1][ry + 1][m],                               b12 = sMed[1][ry + 1][m + 2];
            float b20 = sMed[1][ry + 2][m], b21 = sMed[1][ry + 2][m + 1], b22 = sMed[1][ry + 2][m + 2];
            float gxR = (b02 + b12 + b22 - b00 - b10 - b20) * inv3;
            float gyR = (b00 + b01 + b02 - b20 - b21 - b22) * inv3;
            float sR  = gxR * gxR + gyR * gyR;
            // gmap = (2*gI*gR + c)/(sI + sR + c);  gI*gR = sqrt(sI*sR)
            float num = 2.0f * sqrtf(sI * sR) + C_GMS;
            float den = sI + sR + C_GMS;
            acc += 1.0f - num / den;
        }
    }

    // ---- block reduction ----
#pragma unroll
    for (int o = 16; o > 0; o >>= 1) acc += __shfl_down_sync(0xffffffffu, acc, o);
    __shared__ float wsum[8];
    if ((tid & 31) == 0) wsum[tid >> 5] = acc;
    __syncthreads();
    if (tid < 8) {
        float s = wsum[tid];
#pragma unroll
        for (int o = 4; o > 0; o >>= 1) s += __shfl_down_sync(0xffu, s, o);
        if (tid == 0) atomicAdd(&g_accum, (double)s * (double)weight);
    }
}

// ---------------------------------------------------------------------------
extern "C" void kernel_launch(void* const* d_in, const int* in_sizes, int n_in,
                              void* d_out, int out_size) {
    const float* Ii = (const float*)d_in[0];
    const float* Ir = (const float*)d_in[1];
    float* out = (float*)d_out;

    zero_accum_k<<<1, 1>>>();

    // grayscale at scale 0
    {
        int n4 = NB * 512 * 512 / 4;
        gray_k<<<(n4 + 255) / 256, 256>>>(Ii, Ir);
    }

    auto launch_gms = [&](int H, int W, int off) {
        dim3 g((W - 2 + 31) / 32, (H - 2 + 31) / 32, NB);
        float w = 1.0f / (4.0f * NB * (float)(H - 2) * (float)(W - 2));
        gms_k<<<g, dim3(32, 8)>>>(H, W, off, w);
    };
    auto launch_pool = [&](int Hin, int Win, int offIn, int offOut) {
        int per_img = NB * (Hin / 2) * (Win / 4);   // out-pixel pairs
        int total = 2 * per_img;
        pool_k<<<(total + 255) / 256, 256>>>(Hin, Win, offIn, offOut);
    };

    launch_gms(512, 512, OFF0);
    launch_pool(512, 512, OFF0, OFF1);
    launch_gms(256, 256, OFF1);
    launch_pool(256, 256, OFF1, OFF2);
    launch_gms(128, 128, OFF2);
    launch_pool(128, 128, OFF2, OFF3);
    launch_gms(64, 64, OFF3);

    finalize_k<<<1, 1>>>(out);
}

// round 7
// speedup vs baseline: 1.1496x; 1.1496x over previous
#include <cuda_runtime.h>

// ---------------------------------------------------------------------------
// MSGMS loss, 4-scale pyramid.
//  Kernel 1 (graypyr_k): grayscale of both images + full avg-pool pyramid in
//                        one pass (gray commutes with avg_pool2 — both linear).
//  Kernel 2 (gms_all_k): ALL 4 scales in one launch. Per 32x32 output tile:
//     stage A: gray tile (36x40, float4-vectorized for interior blocks) -> smem
//     stage B: sorted vertical triples (sort3)
//     stage C: median-of-9 = med3(max3(lo), med3(mi), min3(hi))
//     stage D: Prewitt + gmap (only sqrt(sI*sR) needed) + block reduce
//     -> per-block partial written to g_partial[bid] (NO contended atomics)
//  Kernel 3 (finalize_k): fixed-order sum of partials -> out (deterministic).
// ---------------------------------------------------------------------------

#define C_GMS 0.0026f

static constexpr int NB   = 16;
static constexpr int OFF0 = 0;
static constexpr int OFF1 = OFF0 + 16 * 512 * 512;
static constexpr int OFF2 = OFF1 + 16 * 256 * 256;
static constexpr int OFF3 = OFF2 + 16 * 128 * 128;
static constexpr int GTOT = OFF3 + 16 * 64 * 64;

static constexpr int N0 = 16 * 16 * NB;   // 4096 tiles @512
static constexpr int N1 = 8 * 8 * NB;     // 1024 @256
static constexpr int N2 = 4 * 4 * NB;     // 256  @128
static constexpr int N3 = 2 * 2 * NB;     // 64   @64
static constexpr int NBLK = N0 + N1 + N2 + N3;  // 5440

__device__ float  g_gray[2][GTOT];
__device__ double g_partial[NBLK];

// ---------------------------------------------------------------------------
// Kernel 1: grayscale + 3-level pooled pyramid. Block = one (img-pair) stripe
// of 8 L0 rows x 512 cols. grid = (64 stripes, 16 batch).
// ---------------------------------------------------------------------------
__global__ __launch_bounds__(256) void graypyr_k(const float* __restrict__ Ii,
                                                 const float* __restrict__ Ir) {
    const int s = blockIdx.x;   // stripe 0..63 (L0 rows 8s..8s+7)
    const int b = blockIdx.y;   // batch
    const int tid = threadIdx.x;
    __shared__ float sg[2][8][512];
    __shared__ float s1[2][4][256];
    __shared__ float s2[2][2][128];
    const float inv3 = 1.0f / 3.0f;

    // gray: 2 imgs x 8 rows x 128 float4 = 2048 vec items
    for (int i = tid; i < 2048; i += 256) {
        int img = i >> 10;
        int rem = i & 1023;
        int r   = rem >> 7;
        int c4  = rem & 127;
        const float* base = (img ? Ir : Ii) + (size_t)b * 3 * 512 * 512
                            + (size_t)(s * 8 + r) * 512;
        float4 a = ((const float4*)base)[c4];
        float4 c1 = ((const float4*)(base + 512 * 512))[c4];
        float4 c2 = ((const float4*)(base + 2 * 512 * 512))[c4];
        float4 o = { (a.x + c1.x + c2.x) * inv3, (a.y + c1.y + c2.y) * inv3,
                     (a.z + c1.z + c2.z) * inv3, (a.w + c1.w + c2.w) * inv3 };
        ((float4*)&g_gray[img][(size_t)b * 512 * 512 + (size_t)(s * 8 + r) * 512])[c4] = o;
        ((float4*)&sg[img][r][0])[c4] = o;
    }
    __syncthreads();

    // L1: 2 x 4 x 256 = 2048 outputs
    for (int i = tid; i < 2048; i += 256) {
        int img = i >> 10;
        int rem = i & 1023;
        int r   = rem >> 8;     // 0..3
        int c   = rem & 255;
        float2 t0 = *(const float2*)&sg[img][2 * r][2 * c];
        float2 t1 = *(const float2*)&sg[img][2 * r + 1][2 * c];
        float v = (t0.x + t0.y + t1.x + t1.y) * 0.25f;
        s1[img][r][c] = v;
        g_gray[img][OFF1 + (size_t)b * 256 * 256 + (size_t)(s * 4 + r) * 256 + c] = v;
    }
    __syncthreads();

    // L2: 2 x 2 x 128 = 512 outputs
    for (int i = tid; i < 512; i += 256) {
        int img = i >> 8;
        int rem = i & 255;
        int r   = rem >> 7;     // 0..1
        int c   = rem & 127;
        float2 t0 = *(const float2*)&s1[img][2 * r][2 * c];
        float2 t1 = *(const float2*)&s1[img][2 * r + 1][2 * c];
        float v = (t0.x + t0.y + t1.x + t1.y) * 0.25f;
        s2[img][r][c] = v;
        g_gray[img][OFF2 + (size_t)b * 128 * 128 + (size_t)(s * 2 + r) * 128 + c] = v;
    }
    __syncthreads();

    // L3: 2 x 1 x 64 = 128 outputs
    if (tid < 128) {
        int img = tid >> 6;
        int c   = tid & 63;
        float2 t0 = *(const float2*)&s2[img][0][2 * c];
        float2 t1 = *(const float2*)&s2[img][1][2 * c];
        float v = (t0.x + t0.y + t1.x + t1.y) * 0.25f;
        g_gray[img][OFF3 + (size_t)b * 64 * 64 + (size_t)s * 64 + c] = v;
    }
}

// ---------------------------------------------------------------------------
// Fused GMS tile
// ---------------------------------------------------------------------------
struct Smem {
    union {
        float g[2][36][40];       // gray tile (stage A/B)
        float med[2][34][36];     // medians (stage C/D) — aliased after sync
    } u;
    float lo[2][34][36];
    float mi[2][34][36];
    float hi[2][34][36];
    float wsum[8];
};

__device__ __forceinline__ float med3f(float a, float b, float c) {
    return fmaxf(fminf(a, b), fminf(fmaxf(a, b), c));
}
__device__ __forceinline__ void sort3f(float& a, float& b, float& c) {
    float t;
    t = fminf(a, b); b = fmaxf(a, b); a = t;
    t = fminf(b, c); c = fmaxf(b, c); b = t;
    t = fminf(a, b); b = fmaxf(a, b); a = t;
}

template <int H, int W, int LOGT>
__device__ __forceinline__ void gms_tile(Smem& sm, int local, int off, int gbid) {
    constexpr int T = 1 << LOGT;               // tiles per dim
    const int bx = local & (T - 1);
    const int by = (local >> LOGT) & (T - 1);
    const int b  = local >> (2 * LOGT);
    const int OX = bx * 32;
    const int OY = by * 32;
    const int tid = threadIdx.x;

    const float* __restrict__ g0 = &g_gray[0][off + (size_t)b * H * W];
    const float* __restrict__ g1 = &g_gray[1][off + (size_t)b * H * W];

    const bool interior = (OX >= 4) && (OX + 36 <= W) && (OY >= 1) && (OY + 35 <= H);

    // ---- Stage A: gray tile (rows OY-1..OY+34, cols OX-4..OX+35) ----
    if (interior) {
        for (int i = tid; i < 720; i += 256) {     // 2 img x 36 rows x 10 float4
            int img = (i >= 360);
            int rem = i - img * 360;
            int r   = rem / 10;
            int c4  = rem - r * 10;
            const float* base = (img ? g1 : g0) + (size_t)(OY - 1 + r) * W + (OX - 4);
            ((float4*)&sm.u.g[img][r][0])[c4] = ((const float4*)base)[c4];
        }
    } else {
        for (int i = tid; i < 2880; i += 256) {    // 2 x 36 x 40 scalars, guarded
            int img = (i >= 1440);
            int rem = i - img * 1440;
            int r   = rem / 40;
            int cc  = rem - r * 40;
            int gy = OY - 1 + r;
            int gx = OX - 4 + cc;
            const float* g = img ? g1 : g0;
            float v = ((unsigned)gy < (unsigned)H && (unsigned)gx < (unsigned)W)
                        ? __ldg(g + (size_t)gy * W + gx) : 0.0f;
            sm.u.g[img][r][cc] = v;
        }
    }
    __syncthreads();

    // ---- Stage B: sorted vertical triples (rows r..r+2, col c+3) ----
    for (int i = tid; i < 2448; i += 256) {        // 2 x 34 x 36
        int img = (i >= 1224);
        int rem = i - img * 1224;
        int r   = rem / 36;
        int c   = rem - r * 36;
        float v0 = sm.u.g[img][r][c + 3];
        float v1 = sm.u.g[img][r + 1][c + 3];
        float v2 = sm.u.g[img][r + 2][c + 3];
        sort3f(v0, v1, v2);
        sm.lo[img][r][c] = v0;
        sm.mi[img][r][c] = v1;
        sm.hi[img][r][c] = v2;
    }
    __syncthreads();

    // ---- Stage C: median-of-9 (overwrites gray tile storage) ----
    for (int i = tid; i < 2312; i += 256) {        // 2 x 34 x 34
        int img = (i >= 1156);
        int rem = i - img * 1156;
        int r   = rem / 34;
        int m   = rem - r * 34;
        float lo = fmaxf(fmaxf(sm.lo[img][r][m], sm.lo[img][r][m + 1]), sm.lo[img][r][m + 2]);
        float mi = med3f(sm.mi[img][r][m], sm.mi[img][r][m + 1], sm.mi[img][r][m + 2]);
        float hi = fminf(fminf(sm.hi[img][r][m], sm.hi[img][r][m + 1]), sm.hi[img][r][m + 2]);
        sm.u.med[img][r][m] = med3f(lo, mi, hi);
    }
    __syncthreads();

    // ---- Stage D: Prewitt + GMS + reduce ----
    const float inv3 = 1.0f / 3.0f;
    const int tx = tid & 31;
    const int ty = tid >> 5;
    float acc = 0.0f;
#pragma unroll
    for (int v = 0; v < 4; v++) {
        int ry = ty + 8 * v;
        bool valid = interior || ((OY + ry < H - 2) && (OX + tx < W - 2));
        if (valid) {
            int m = tx;
            float a00 = sm.u.med[0][ry][m],     a01 = sm.u.med[0][ry][m + 1],     a02 = sm.u.med[0][ry][m + 2];
            float a10 = sm.u.med[0][ry + 1][m],                                   a12 = sm.u.med[0][ry + 1][m + 2];
            float a20 = sm.u.med[0][ry + 2][m], a21 = sm.u.med[0][ry + 2][m + 1], a22 = sm.u.med[0][ry + 2][m + 2];
            float gxI = (a02 + a12 + a22 - a00 - a10 - a20) * inv3;
            float gyI = (a00 + a01 + a02 - a20 - a21 - a22) * inv3;
            float sI  = gxI * gxI + gyI * gyI;
            float b00 = sm.u.med[1][ry][m],     b01 = sm.u.med[1][ry][m + 1],     b02 = sm.u.med[1][ry][m + 2];
            float b10 = sm.u.med[1][ry + 1][m],                                   b12 = sm.u.med[1][ry + 1][m + 2];
            float b20 = sm.u.med[1][ry + 2][m], b21 = sm.u.med[1][ry + 2][m + 1], b22 = sm.u.med[1][ry + 2][m + 2];
            float gxR = (b02 + b12 + b22 - b00 - b10 - b20) * inv3;
            float gyR = (b00 + b01 + b02 - b20 - b21 - b22) * inv3;
            float sR  = gxR * gxR + gyR * gyR;
            float num = 2.0f * sqrtf(sI * sR) + C_GMS;
            float den = sI + sR + C_GMS;
            acc += 1.0f - num / den;
        }
    }

#pragma unroll
    for (int o = 16; o > 0; o >>= 1) acc += __shfl_down_sync(0xffffffffu, acc, o);
    if ((tid & 31) == 0) sm.wsum[tid >> 5] = acc;
    __syncthreads();
    if (tid < 8) {
        float s = sm.wsum[tid];
#pragma unroll
        for (int o = 4; o > 0; o >>= 1) s += __shfl_down_sync(0xffu, s, o);
        if (tid == 0) {
            constexpr float wgt = 1.0f / (4.0f * (float)NB * (float)(H - 2) * (float)(W - 2));
            g_partial[gbid] = (double)(s * wgt);
        }
    }
}

__global__ __launch_bounds__(256) void gms_all_k() {
    __shared__ Smem sm;
    const int bid = blockIdx.x;
    if (bid < N0) {
        gms_tile<512, 512, 4>(sm, bid, OFF0, bid);
    } else if (bid < N0 + N1) {
        gms_tile<256, 256, 3>(sm, bid - N0, OFF1, bid);
    } else if (bid < N0 + N1 + N2) {
        gms_tile<128, 128, 2>(sm, bid - N0 - N1, OFF2, bid);
    } else {
        gms_tile<64, 64, 1>(sm, bid - N0 - N1 - N2, OFF3, bid);
    }
}

// ---------------------------------------------------------------------------
// Kernel 3: deterministic fixed-order reduction of per-block partials.
// ---------------------------------------------------------------------------
__global__ __launch_bounds__(256) void finalize_k(float* __restrict__ out) {
    __shared__ double ws[8];
    double s = 0.0;
    for (int i = threadIdx.x; i < NBLK; i += 256) s += g_partial[i];
#pragma unroll
    for (int o = 16; o > 0; o >>= 1) s += __shfl_down_sync(0xffffffffu, s, o);
    if ((threadIdx.x & 31) == 0) ws[threadIdx.x >> 5] = s;
    __syncthreads();
    if (threadIdx.x < 8) {
        double t = ws[threadIdx.x];
#pragma unroll
        for (int o = 4; o > 0; o >>= 1) t += __shfl_down_sync(0xffu, t, o);
        if (threadIdx.x == 0) out[0] = (float)t;
    }
}

// ---------------------------------------------------------------------------
extern "C" void kernel_launch(void* const* d_in, const int* in_sizes, int n_in,
                              void* d_out, int out_size) {
    const float* Ii = (const float*)d_in[0];
    const float* Ir = (const float*)d_in[1];
    float* out = (float*)d_out;

    graypyr_k<<<dim3(64, NB), 256>>>(Ii, Ir);
    gms_all_k<<<NBLK, 256>>>();
    finalize_k<<<1, 256>>>(out);
}

// round 8
// speedup vs baseline: 1.3533x; 1.1772x over previous
#include <cuda_runtime.h>

// ---------------------------------------------------------------------------
// MSGMS loss, 4-scale pyramid.
//  Kernel 1 (graypyr_k): fused grayscale + full avg-pool pyramid, low-smem
//                        (10KB) register-fused gray->L1; high occupancy.
//  Kernel 2 (gms_all_k): ALL 4 scales in one launch; LDS.128-vectorized
//                        median (stage C) and Prewitt/GMS (stage D).
//  Kernel 3 (finalize_k): fixed-order deterministic sum of block partials.
// ---------------------------------------------------------------------------

#define C_GMS 0.0026f

static constexpr int NB   = 16;
static constexpr int HW0  = 512 * 512;
static constexpr int OFF0 = 0;
static constexpr int OFF1 = OFF0 + 16 * 512 * 512;
static constexpr int OFF2 = OFF1 + 16 * 256 * 256;
static constexpr int OFF3 = OFF2 + 16 * 128 * 128;
static constexpr int GTOT = OFF3 + 16 * 64 * 64;

static constexpr int N0 = 16 * 16 * NB;   // 4096 tiles @512
static constexpr int N1 = 8 * 8 * NB;     // 1024 @256
static constexpr int N2 = 4 * 4 * NB;     // 256  @128
static constexpr int N3 = 2 * 2 * NB;     // 64   @64
static constexpr int NBLK = N0 + N1 + N2 + N3;  // 5440

__device__ float  g_gray[2][GTOT];
__device__ double g_partial[NBLK];

// ---------------------------------------------------------------------------
// Kernel 1: grayscale + pooled pyramid. Block = 8 L0 rows x 512 cols stripe.
// Each thread task: one (img, L1-row, col-pair) -> 6 LDG.128, writes 2 float4
// of L0 gray + float2 of L1. Smem only holds L1/L2 for further pooling.
// ---------------------------------------------------------------------------
__global__ __launch_bounds__(256) void graypyr_k(const float* __restrict__ Ii,
                                                 const float* __restrict__ Ir) {
    const int s = blockIdx.x;   // stripe 0..63 (L0 rows 8s..8s+7)
    const int b = blockIdx.y;   // batch
    const int tid = threadIdx.x;
    __shared__ float s1[2][4][256];
    __shared__ float s2[2][2][128];
    const float inv3 = 1.0f / 3.0f;

    // gray + L1: 2 img x 4 L1 rows x 128 col-pairs = 1024 tasks
    for (int i = tid; i < 1024; i += 256) {
        int img = i >> 9;
        int rem = i & 511;
        int r1  = rem >> 7;      // L1 row 0..3
        int k   = rem & 127;     // col-pair (L0 cols 4k..4k+3)
        const float* base = (img ? Ir : Ii) + (size_t)b * 3 * HW0
                            + (size_t)(s * 8 + 2 * r1) * 512 + 4 * k;
        float4 a0 = *(const float4*)base;
        float4 a1 = *(const float4*)(base + HW0);
        float4 a2 = *(const float4*)(base + 2 * HW0);
        float4 g0 = { (a0.x + a1.x + a2.x) * inv3, (a0.y + a1.y + a2.y) * inv3,
                      (a0.z + a1.z + a2.z) * inv3, (a0.w + a1.w + a2.w) * inv3 };
        const float* baseb = base + 512;
        float4 c0 = *(const float4*)baseb;
        float4 c1 = *(const float4*)(baseb + HW0);
        float4 c2 = *(const float4*)(baseb + 2 * HW0);
        float4 g1 = { (c0.x + c1.x + c2.x) * inv3, (c0.y + c1.y + c2.y) * inv3,
                      (c0.z + c1.z + c2.z) * inv3, (c0.w + c1.w + c2.w) * inv3 };
        float* L0 = &g_gray[img][(size_t)b * HW0 + (size_t)(s * 8 + 2 * r1) * 512 + 4 * k];
        *(float4*)L0         = g0;
        *(float4*)(L0 + 512) = g1;
        float2 l1 = { (g0.x + g0.y + g1.x + g1.y) * 0.25f,
                      (g0.z + g0.w + g1.z + g1.w) * 0.25f };
        *(float2*)&s1[img][r1][2 * k] = l1;
        *(float2*)&g_gray[img][OFF1 + (size_t)b * 256 * 256 + (size_t)(s * 4 + r1) * 256 + 2 * k] = l1;
    }
    __syncthreads();

    // L2: 2 x 2 x 128 = 512 outputs
    for (int i = tid; i < 512; i += 256) {
        int img = i >> 8;
        int rem = i & 255;
        int r   = rem >> 7;     // 0..1
        int c   = rem & 127;
        float2 t0 = *(const float2*)&s1[img][2 * r][2 * c];
        float2 t1 = *(const float2*)&s1[img][2 * r + 1][2 * c];
        float v = (t0.x + t0.y + t1.x + t1.y) * 0.25f;
        s2[img][r][c] = v;
        g_gray[img][OFF2 + (size_t)b * 128 * 128 + (size_t)(s * 2 + r) * 128 + c] = v;
    }
    __syncthreads();

    // L3: 2 x 1 x 64 = 128 outputs
    if (tid < 128) {
        int img = tid >> 6;
        int c   = tid & 63;
        float2 t0 = *(const float2*)&s2[img][0][2 * c];
        float2 t1 = *(const float2*)&s2[img][1][2 * c];
        float v = (t0.x + t0.y + t1.x + t1.y) * 0.25f;
        g_gray[img][OFF3 + (size_t)b * 64 * 64 + (size_t)s * 64 + c] = v;
    }
}

// ---------------------------------------------------------------------------
// Fused GMS tile. All stage arrays use stride 40 so every 4-col quad is
// 16B-aligned for LDS.128.
// ---------------------------------------------------------------------------
struct Smem {
    union {
        float g[2][36][40];       // gray tile (stages A/B)
        float med[2][34][40];     // medians (stages C/D) — aliased after sync
    } u;
    float lo[2][34][40];
    float mi[2][34][40];
    float hi[2][34][40];
    float wsum[8];
};

__device__ __forceinline__ float med3f(float a, float b, float c) {
    return fmaxf(fminf(a, b), fminf(fmaxf(a, b), c));
}
__device__ __forceinline__ void sort3f(float& a, float& b, float& c) {
    float t;
    t = fminf(a, b); b = fmaxf(a, b); a = t;
    t = fminf(b, c); c = fmaxf(b, c); b = t;
    t = fminf(a, b); b = fmaxf(a, b); a = t;
}

template <int H, int W, int LOGT>
__device__ __forceinline__ void gms_tile(Smem& sm, int local, int off, int gbid) {
    constexpr int T = 1 << LOGT;               // tiles per dim
    const int bx = local & (T - 1);
    const int by = (local >> LOGT) & (T - 1);
    const int b  = local >> (2 * LOGT);
    const int OX = bx * 32;
    const int OY = by * 32;
    const int tid = threadIdx.x;

    const float* __restrict__ g0 = &g_gray[0][off + (size_t)b * H * W];
    const float* __restrict__ g1 = &g_gray[1][off + (size_t)b * H * W];

    const bool interior = (OX >= 4) && (OX + 36 <= W) && (OY >= 1) && (OY + 35 <= H);

    // ---- Stage A: gray tile (rows OY-1..OY+34, cols OX-4..OX+35) ----
    if (interior) {
        for (int i = tid; i < 720; i += 256) {     // 2 img x 36 rows x 10 float4
            int img = (i >= 360);
            int rem = i - img * 360;
            int r   = rem / 10;
            int c4  = rem - r * 10;
            const float* base = (img ? g1 : g0) + (size_t)(OY - 1 + r) * W + (OX - 4);
            ((float4*)&sm.u.g[img][r][0])[c4] = ((const float4*)base)[c4];
        }
    } else {
        for (int i = tid; i < 2880; i += 256) {    // 2 x 36 x 40 scalars, guarded
            int img = (i >= 1440);
            int rem = i - img * 1440;
            int r   = rem / 40;
            int cc  = rem - r * 40;
            int gy = OY - 1 + r;
            int gx = OX - 4 + cc;
            const float* g = img ? g1 : g0;
            float v = ((unsigned)gy < (unsigned)H && (unsigned)gx < (unsigned)W)
                        ? __ldg(g + (size_t)gy * W + gx) : 0.0f;
            sm.u.g[img][r][cc] = v;
        }
    }
    __syncthreads();

    // ---- Stage B: sorted vertical triples; triple col c <- gray col c+3 ----
    for (int i = tid; i < 2448; i += 256) {        // 2 x 34 x 36
        int img = (i >= 1224);
        int rem = i - img * 1224;
        int r   = rem / 36;
        int c   = rem - r * 36;
        float v0 = sm.u.g[img][r][c + 3];
        float v1 = sm.u.g[img][r + 1][c + 3];
        float v2 = sm.u.g[img][r + 2][c + 3];
        sort3f(v0, v1, v2);
        sm.lo[img][r][c] = v0;
        sm.mi[img][r][c] = v1;
        sm.hi[img][r][c] = v2;
    }
    __syncthreads();

    // ---- Stage C: 4 medians per task via 6 aligned LDS.128 ----
    for (int i = tid; i < 612; i += 256) {         // 2 img x 34 rows x 9 quads
        int img = i / 306;
        int rem = i - img * 306;
        int r   = rem / 9;
        int k   = rem - r * 9;
        int c0  = 4 * k;
        float l[8], m[8], h[8];
        *(float4*)&l[0] = *(const float4*)&sm.lo[img][r][c0];
        *(float4*)&l[4] = *(const float4*)&sm.lo[img][r][c0 + 4];
        *(float4*)&m[0] = *(const float4*)&sm.mi[img][r][c0];
        *(float4*)&m[4] = *(const float4*)&sm.mi[img][r][c0 + 4];
        *(float4*)&h[0] = *(const float4*)&sm.hi[img][r][c0];
        *(float4*)&h[4] = *(const float4*)&sm.hi[img][r][c0 + 4];
        float out[4];
#pragma unroll
        for (int j = 0; j < 4; j++) {
            float lo = fmaxf(fmaxf(l[j], l[j + 1]), l[j + 2]);
            float mi = med3f(m[j], m[j + 1], m[j + 2]);
            float hi = fminf(fminf(h[j], h[j + 1]), h[j + 2]);
            out[j] = med3f(lo, mi, hi);
        }
        *(float4*)&sm.u.med[img][r][c0] = *(float4*)&out[0];
    }
    __syncthreads();

    // ---- Stage D: Prewitt + GMS, 4 pixels per thread via 12 LDS.128 ----
    // gmap with unscaled gradients: (2*sqrt(tI*tR) + 9c)/(tI + tR + 9c)
    const float C9 = 9.0f * C_GMS;
    const int q   = tid & 7;          // col quad: output cols OX+4q..OX+4q+3
    const int row = tid >> 3;         // output row OY+row
    float t[2][4];
#pragma unroll
    for (int img = 0; img < 2; img++) {
        float r0[8], r1[8], r2[8];
        *(float4*)&r0[0] = *(const float4*)&sm.u.med[img][row][4 * q];
        *(float4*)&r0[4] = *(const float4*)&sm.u.med[img][row][4 * q + 4];
        *(float4*)&r1[0] = *(const float4*)&sm.u.med[img][row + 1][4 * q];
        *(float4*)&r1[4] = *(const float4*)&sm.u.med[img][row + 1][4 * q + 4];
        *(float4*)&r2[0] = *(const float4*)&sm.u.med[img][row + 2][4 * q];
        *(float4*)&r2[4] = *(const float4*)&sm.u.med[img][row + 2][4 * q + 4];
        float cs[6];
#pragma unroll
        for (int c = 0; c < 6; c++) cs[c] = r0[c] + r1[c] + r2[c];
#pragma unroll
        for (int j = 0; j < 4; j++) {
            float u = cs[j + 2] - cs[j];
            float v = (r0[j] + r0[j + 1] + r0[j + 2]) - (r2[j] + r2[j + 1] + r2[j + 2]);
            t[img][j] = u * u + v * v;
        }
    }
    float acc = 0.0f;
#pragma unroll
    for (int j = 0; j < 4; j++) {
        bool valid = interior || ((OY + row < H - 2) && (OX + 4 * q + j < W - 2));
        if (valid) {
            float num = 2.0f * sqrtf(t[0][j] * t[1][j]) + C9;
            float den = t[0][j] + t[1][j] + C9;
            acc += 1.0f - num / den;
        }
    }

    // ---- block reduction ----
#pragma unroll
    for (int o = 16; o > 0; o >>= 1) acc += __shfl_down_sync(0xffffffffu, acc, o);
    if ((tid & 31) == 0) sm.wsum[tid >> 5] = acc;
    __syncthreads();
    if (tid < 8) {
        float s = sm.wsum[tid];
#pragma unroll
        for (int o = 4; o > 0; o >>= 1) s += __shfl_down_sync(0xffu, s, o);
        if (tid == 0) {
            constexpr float wgt = 1.0f / (4.0f * (float)NB * (float)(H - 2) * (float)(W - 2));
            g_partial[gbid] = (double)(s * wgt);
        }
    }
}

__global__ __launch_bounds__(256) void gms_all_k() {
    __shared__ Smem sm;
    const int bid = blockIdx.x;
    if (bid < N0) {
        gms_tile<512, 512, 4>(sm, bid, OFF0, bid);
    } else if (bid < N0 + N1) {
        gms_tile<256, 256, 3>(sm, bid - N0, OFF1, bid);
    } else if (bid < N0 + N1 + N2) {
        gms_tile<128, 128, 2>(sm, bid - N0 - N1, OFF2, bid);
    } else {
        gms_tile<64, 64, 1>(sm, bid - N0 - N1 - N2, OFF3, bid);
    }
}

// ---------------------------------------------------------------------------
// Kernel 3: deterministic fixed-order reduction of per-block partials.
// ---------------------------------------------------------------------------
__global__ __launch_bounds__(256) void finalize_k(float* __restrict__ out) {
    __shared__ double ws[8];
    double s = 0.0;
    for (int i = threadIdx.x; i < NBLK; i += 256) s += g_partial[i];
#pragma unroll
    for (int o = 16; o > 0; o >>= 1) s += __shfl_down_sync(0xffffffffu, s, o);
    if ((threadIdx.x & 31) == 0) ws[threadIdx.x >> 5] = s;
    __syncthreads();
    if (threadIdx.x < 8) {
        double t = ws[threadIdx.x];
#pragma unroll
        for (int o = 4; o > 0; o >>= 1) t += __shfl_down_sync(0xffu, t, o);
        if (threadIdx.x == 0) out[0] = (float)t;
    }
}

// ---------------------------------------------------------------------------
extern "C" void kernel_launch(void* const* d_in, const int* in_sizes, int n_in,
                              void* d_out, int out_size) {
    const float* Ii = (const float*)d_in[0];
    const float* Ir = (const float*)d_in[1];
    float* out = (float*)d_out;

    graypyr_k<<<dim3(64, NB), 256>>>(Ii, Ir);
    gms_all_k<<<NBLK, 256>>>();
    finalize_k<<<1, 256>>>(out);
}

// round 9
// speedup vs baseline: 1.5010x; 1.1091x over previous
#include <cuda_runtime.h>

// ---------------------------------------------------------------------------
// MSGMS loss, 4-scale pyramid.
//  Kernel 1 (graypyr_k): fused grayscale + avg-pool pyramid (unchanged, ~68% DRAM).
//  Kernel 2 (gms_all_k): ALL 4 scales, one launch. Per 32x32 output tile:
//     stage A : gray tile (36x48, float4 interior path, zero-filled tail) -> smem
//     stage BC: FUSED vertical sort3 + horizontal median-of-9 combine,
//               4 medians/task from 6 LDS.128 + 3 LDS (no lo/mi/hi arrays)
//     stage D : Prewitt + gmap (only sqrt(tI*tR) needed) + block reduce
//     -> per-block partial in g_partial[bid] (no contended atomics)
//  Kernel 3 (finalize_k): fixed-order deterministic sum.
// ---------------------------------------------------------------------------

#define C_GMS 0.0026f

static constexpr int NB   = 16;
static constexpr int HW0  = 512 * 512;
static constexpr int OFF0 = 0;
static constexpr int OFF1 = OFF0 + 16 * 512 * 512;
static constexpr int OFF2 = OFF1 + 16 * 256 * 256;
static constexpr int OFF3 = OFF2 + 16 * 128 * 128;
static constexpr int GTOT = OFF3 + 16 * 64 * 64;

static constexpr int N0 = 16 * 16 * NB;   // 4096 tiles @512
static constexpr int N1 = 8 * 8 * NB;     // 1024 @256
static constexpr int N2 = 4 * 4 * NB;     // 256  @128
static constexpr int N3 = 2 * 2 * NB;     // 64   @64
static constexpr int NBLK = N0 + N1 + N2 + N3;  // 5440

__device__ float  g_gray[2][GTOT];
__device__ double g_partial[NBLK];

// ---------------------------------------------------------------------------
// Kernel 1: grayscale + pooled pyramid (register-fused gray->L1, 10KB smem).
// ---------------------------------------------------------------------------
__global__ __launch_bounds__(256) void graypyr_k(const float* __restrict__ Ii,
                                                 const float* __restrict__ Ir) {
    const int s = blockIdx.x;   // stripe 0..63 (L0 rows 8s..8s+7)
    const int b = blockIdx.y;   // batch
    const int tid = threadIdx.x;
    __shared__ float s1[2][4][256];
    __shared__ float s2[2][2][128];
    const float inv3 = 1.0f / 3.0f;

    // gray + L1: 2 img x 4 L1 rows x 128 col-pairs = 1024 tasks
    for (int i = tid; i < 1024; i += 256) {
        int img = i >> 9;
        int rem = i & 511;
        int r1  = rem >> 7;      // L1 row 0..3
        int k   = rem & 127;     // col-pair (L0 cols 4k..4k+3)
        const float* base = (img ? Ir : Ii) + (size_t)b * 3 * HW0
                            + (size_t)(s * 8 + 2 * r1) * 512 + 4 * k;
        float4 a0 = *(const float4*)base;
        float4 a1 = *(const float4*)(base + HW0);
        float4 a2 = *(const float4*)(base + 2 * HW0);
        float4 g0 = { (a0.x + a1.x + a2.x) * inv3, (a0.y + a1.y + a2.y) * inv3,
                      (a0.z + a1.z + a2.z) * inv3, (a0.w + a1.w + a2.w) * inv3 };
        const float* baseb = base + 512;
        float4 c0 = *(const float4*)baseb;
        float4 c1 = *(const float4*)(baseb + HW0);
        float4 c2 = *(const float4*)(baseb + 2 * HW0);
        float4 g1 = { (c0.x + c1.x + c2.x) * inv3, (c0.y + c1.y + c2.y) * inv3,
                      (c0.z + c1.z + c2.z) * inv3, (c0.w + c1.w + c2.w) * inv3 };
        float* L0 = &g_gray[img][(size_t)b * HW0 + (size_t)(s * 8 + 2 * r1) * 512 + 4 * k];
        *(float4*)L0         = g0;
        *(float4*)(L0 + 512) = g1;
        float2 l1 = { (g0.x + g0.y + g1.x + g1.y) * 0.25f,
                      (g0.z + g0.w + g1.z + g1.w) * 0.25f };
        *(float2*)&s1[img][r1][2 * k] = l1;
        *(float2*)&g_gray[img][OFF1 + (size_t)b * 256 * 256 + (size_t)(s * 4 + r1) * 256 + 2 * k] = l1;
    }
    __syncthreads();

    // L2
    for (int i = tid; i < 512; i += 256) {
        int img = i >> 8;
        int rem = i & 255;
        int r   = rem >> 7;
        int c   = rem & 127;
        float2 t0 = *(const float2*)&s1[img][2 * r][2 * c];
        float2 t1 = *(const float2*)&s1[img][2 * r + 1][2 * c];
        float v = (t0.x + t0.y + t1.x + t1.y) * 0.25f;
        s2[img][r][c] = v;
        g_gray[img][OFF2 + (size_t)b * 128 * 128 + (size_t)(s * 2 + r) * 128 + c] = v;
    }
    __syncthreads();

    // L3
    if (tid < 128) {
        int img = tid >> 6;
        int c   = tid & 63;
        float2 t0 = *(const float2*)&s2[img][0][2 * c];
        float2 t1 = *(const float2*)&s2[img][1][2 * c];
        float v = (t0.x + t0.y + t1.x + t1.y) * 0.25f;
        g_gray[img][OFF3 + (size_t)b * 64 * 64 + (size_t)s * 64 + c] = v;
    }
}

// ---------------------------------------------------------------------------
// Fused GMS tile. gray stride 48 (tail quads zeroed), med stride 40; all
// quad accesses 16B-aligned for LDS.128/STS.128.
// ---------------------------------------------------------------------------
struct Smem {
    float g[2][36][48];     // gray: row r = gray row OY-1+r, col cc = OX-4+cc
    float med[2][34][40];   // median-of-9 tile
    float wsum[8];
};

__device__ __forceinline__ float med3f(float a, float b, float c) {
    return fmaxf(fminf(a, b), fminf(fmaxf(a, b), c));
}
__device__ __forceinline__ void sort3f(float& a, float& b, float& c) {
    float t;
    t = fminf(a, b); b = fmaxf(a, b); a = t;
    t = fminf(b, c); c = fmaxf(b, c); b = t;
    t = fminf(a, b); b = fmaxf(a, b); a = t;
}

template <int H, int W, int LOGT>
__device__ __forceinline__ void gms_tile(Smem& sm, int local, int off, int gbid) {
    constexpr int T = 1 << LOGT;
    const int bx = local & (T - 1);
    const int by = (local >> LOGT) & (T - 1);
    const int b  = local >> (2 * LOGT);
    const int OX = bx * 32;
    const int OY = by * 32;
    const int tid = threadIdx.x;

    const float* __restrict__ g0 = &g_gray[0][off + (size_t)b * H * W];
    const float* __restrict__ g1 = &g_gray[1][off + (size_t)b * H * W];

    const bool interior = (OX >= 4) && (OX + 36 <= W) && (OY >= 1) && (OY + 35 <= H);

    // ---- Stage A: gray tile. Interior: 720 float4 loads + 144 zero quads ----
    if (interior) {
        for (int i = tid; i < 864; i += 256) {
            if (i < 720) {               // 2 img x 36 rows x 10 quads
                int img = (i >= 360);
                int rem = i - img * 360;
                int r   = rem / 10;
                int c4  = rem - r * 10;
                const float* base = (img ? g1 : g0) + (size_t)(OY - 1 + r) * W + (OX - 4);
                *(float4*)&sm.g[img][r][4 * c4] = ((const float4*)base)[c4];
            } else {                     // zero-fill quads 10,11 (cc 40..47)
                int j   = i - 720;       // 0..143 = 2 img x 36 rows x 2 quads
                int img = (j >= 72);
                int rem = j - img * 72;
                int r   = rem >> 1;
                int k   = rem & 1;
                float4 z = {0.f, 0.f, 0.f, 0.f};
                *(float4*)&sm.g[img][r][40 + 4 * k] = z;
            }
        }
    } else {
        for (int i = tid; i < 3456; i += 256) {    // 2 x 36 x 48 scalars, guarded
            int img = (i >= 1728);
            int rem = i - img * 1728;
            int r   = rem / 48;
            int cc  = rem - r * 48;
            int gy = OY - 1 + r;
            int gx = OX - 4 + cc;
            const float* g = img ? g1 : g0;
            float v = ((unsigned)gy < (unsigned)H && (unsigned)gx < (unsigned)W)
                        ? __ldg(g + (size_t)gy * W + gx) : 0.0f;
            sm.g[img][r][cc] = v;
        }
    }
    __syncthreads();

    // ---- Stage BC (fused): 4 medians/task from 6 LDS.128 + 3 LDS ----
    // Median (r, c0+m) uses vertical-sorted triples of gray cols cc=c0+3+m..c0+5+m.
    for (int i = tid; i < 612; i += 256) {         // 2 img x 34 rows x 9 quads
        int img = i / 306;
        int rem = i - img * 306;
        int r   = rem / 9;
        int q   = rem - 9 * r;
        int c0  = 4 * q;
        float f[3][8], e[3];
#pragma unroll
        for (int rr = 0; rr < 3; rr++) {
            *(float4*)&f[rr][0] = *(const float4*)&sm.g[img][r + rr][c0];
            *(float4*)&f[rr][4] = *(const float4*)&sm.g[img][r + rr][c0 + 4];
            e[rr] = sm.g[img][r + rr][c0 + 8];
        }
        float lo[6], mi[6], hi[6];
#pragma unroll
        for (int j = 0; j < 6; j++) {              // triple at gray cc = c0+3+j
            float v0 = (j < 5) ? f[0][3 + j] : e[0];
            float v1 = (j < 5) ? f[1][3 + j] : e[1];
            float v2 = (j < 5) ? f[2][3 + j] : e[2];
            sort3f(v0, v1, v2);
            lo[j] = v0; mi[j] = v1; hi[j] = v2;
        }
        float out[4];
#pragma unroll
        for (int m = 0; m < 4; m++) {
            float L = fmaxf(fmaxf(lo[m], lo[m + 1]), lo[m + 2]);
            float M = med3f(mi[m], mi[m + 1], mi[m + 2]);
            float Hh = fminf(fminf(hi[m], hi[m + 1]), hi[m + 2]);
            out[m] = med3f(L, M, Hh);
        }
        *(float4*)&sm.med[img][r][c0] = *(float4*)&out[0];
    }
    __syncthreads();

    // ---- Stage D: Prewitt + GMS, 4 px/thread via 12 LDS.128 ----
    // gmap with unscaled gradients: (2*sqrt(tI*tR) + 9c)/(tI + tR + 9c)
    const float C9 = 9.0f * C_GMS;
    const int q   = tid & 7;          // col quad: output cols OX+4q..OX+4q+3
    const int row = tid >> 3;         // output row OY+row
    float t[2][4];
#pragma unroll
    for (int img = 0; img < 2; img++) {
        float r0[8], r1[8], r2[8];
        *(float4*)&r0[0] = *(const float4*)&sm.med[img][row][4 * q];
        *(float4*)&r0[4] = *(const float4*)&sm.med[img][row][4 * q + 4];
        *(float4*)&r1[0] = *(const float4*)&sm.med[img][row + 1][4 * q];
        *(float4*)&r1[4] = *(const float4*)&sm.med[img][row + 1][4 * q + 4];
        *(float4*)&r2[0] = *(const float4*)&sm.med[img][row + 2][4 * q];
        *(float4*)&r2[4] = *(const float4*)&sm.med[img][row + 2][4 * q + 4];
        float cs[6];
#pragma unroll
        for (int c = 0; c < 6; c++) cs[c] = r0[c] + r1[c] + r2[c];
#pragma unroll
        for (int j = 0; j < 4; j++) {
            float u = cs[j + 2] - cs[j];
            float v = (r0[j] + r0[j + 1] + r0[j + 2]) - (r2[j] + r2[j + 1] + r2[j + 2]);
            t[img][j] = u * u + v * v;
        }
    }
    float acc = 0.0f;
#pragma unroll
    for (int j = 0; j < 4; j++) {
        bool valid = interior || ((OY + row < H - 2) && (OX + 4 * q + j < W - 2));
        if (valid) {
            float num = 2.0f * sqrtf(t[0][j] * t[1][j]) + C9;
            float den = t[0][j] + t[1][j] + C9;
            acc += 1.0f - num / den;
        }
    }

    // ---- block reduction ----
#pragma unroll
    for (int o = 16; o > 0; o >>= 1) acc += __shfl_down_sync(0xffffffffu, acc, o);
    if ((tid & 31) == 0) sm.wsum[tid >> 5] = acc;
    __syncthreads();
    if (tid < 8) {
        float s = sm.wsum[tid];
#pragma unroll
        for (int o = 4; o > 0; o >>= 1) s += __shfl_down_sync(0xffu, s, o);
        if (tid == 0) {
            constexpr float wgt = 1.0f / (4.0f * (float)NB * (float)(H - 2) * (float)(W - 2));
            g_partial[gbid] = (double)(s * wgt);
        }
    }
}

__global__ __launch_bounds__(256) void gms_all_k() {
    __shared__ Smem sm;
    const int bid = blockIdx.x;
    if (bid < N0) {
        gms_tile<512, 512, 4>(sm, bid, OFF0, bid);
    } else if (bid < N0 + N1) {
        gms_tile<256, 256, 3>(sm, bid - N0, OFF1, bid);
    } else if (bid < N0 + N1 + N2) {
        gms_tile<128, 128, 2>(sm, bid - N0 - N1, OFF2, bid);
    } else {
        gms_tile<64, 64, 1>(sm, bid - N0 - N1 - N2, OFF3, bid);
    }
}

// ---------------------------------------------------------------------------
// Kernel 3: deterministic fixed-order reduction of per-block partials.
// ---------------------------------------------------------------------------
__global__ __launch_bounds__(256) void finalize_k(float* __restrict__ out) {
    __shared__ double ws[8];
    double s = 0.0;
    for (int i = threadIdx.x; i < NBLK; i += 256) s += g_partial[i];
#pragma unroll
    for (int o = 16; o > 0; o >>= 1) s += __shfl_down_sync(0xffffffffu, s, o);
    if ((threadIdx.x & 31) == 0) ws[threadIdx.x >> 5] = s;
    __syncthreads();
    if (threadIdx.x < 8) {
        double t = ws[threadIdx.x];
#pragma unroll
        for (int o = 4; o > 0; o >>= 1) t += __shfl_down_sync(0xffu, t, o);
        if (threadIdx.x == 0) out[0] = (float)t;
    }
}

// ---------------------------------------------------------------------------
extern "C" void kernel_launch(void* const* d_in, const int* in_sizes, int n_in,
                              void* d_out, int out_size) {
    const float* Ii = (const float*)d_in[0];
    const float* Ir = (const float*)d_in[1];
    float* out = (float*)d_out;

    graypyr_k<<<dim3(64, NB), 256>>>(Ii, Ir);
    gms_all_k<<<NBLK, 256>>>();
    finalize_k<<<1, 256>>>(out);
}

// round 10
// speedup vs baseline: 1.6528x; 1.1011x over previous
#include <cuda_runtime.h>

// ---------------------------------------------------------------------------
// MSGMS loss, 4-scale pyramid.
//  Kernel 1 (graypyr_k): fused grayscale + avg-pool pyramid (~68% DRAM).
//  Kernel 2 (gms_all_k): ALL 4 scales, one launch. Per 32x32 output tile:
//     stage A : gray tile via UNIFIED per-quad loads (vector fast path,
//               per-lane guard only on edge quads, zero OOB rows)
//     stage BC: fused vertical sort3 + horizontal median-of-9 combine
//     stage D : Prewitt + gmap via MUFU intrinsics (rsqrt/fast-div)
//     -> per-block partial in g_partial[bid]
//  Kernel 3 (finalize_k): fixed-order deterministic sum.
// ---------------------------------------------------------------------------

#define C_GMS 0.0026f

static constexpr int NB   = 16;
static constexpr int HW0  = 512 * 512;
static constexpr int OFF0 = 0;
static constexpr int OFF1 = OFF0 + 16 * 512 * 512;
static constexpr int OFF2 = OFF1 + 16 * 256 * 256;
static constexpr int OFF3 = OFF2 + 16 * 128 * 128;
static constexpr int GTOT = OFF3 + 16 * 64 * 64;

static constexpr int N0 = 16 * 16 * NB;   // 4096 tiles @512
static constexpr int N1 = 8 * 8 * NB;     // 1024 @256
static constexpr int N2 = 4 * 4 * NB;     // 256  @128
static constexpr int N3 = 2 * 2 * NB;     // 64   @64
static constexpr int NBLK = N0 + N1 + N2 + N3;  // 5440

__device__ float  g_gray[2][GTOT];
__device__ double g_partial[NBLK];

// ---------------------------------------------------------------------------
// Kernel 1: grayscale + pooled pyramid (register-fused gray->L1, 10KB smem).
// ---------------------------------------------------------------------------
__global__ __launch_bounds__(256) void graypyr_k(const float* __restrict__ Ii,
                                                 const float* __restrict__ Ir) {
    const int s = blockIdx.x;   // stripe 0..63 (L0 rows 8s..8s+7)
    const int b = blockIdx.y;   // batch
    const int tid = threadIdx.x;
    __shared__ float s1[2][4][256];
    __shared__ float s2[2][2][128];
    const float inv3 = 1.0f / 3.0f;

    // gray + L1: 2 img x 4 L1 rows x 128 col-pairs = 1024 tasks
    for (int i = tid; i < 1024; i += 256) {
        int img = i >> 9;
        int rem = i & 511;
        int r1  = rem >> 7;      // L1 row 0..3
        int k   = rem & 127;     // col-pair (L0 cols 4k..4k+3)
        const float* base = (img ? Ir : Ii) + (size_t)b * 3 * HW0
                            + (size_t)(s * 8 + 2 * r1) * 512 + 4 * k;
        float4 a0 = *(const float4*)base;
        float4 a1 = *(const float4*)(base + HW0);
        float4 a2 = *(const float4*)(base + 2 * HW0);
        float4 g0 = { (a0.x + a1.x + a2.x) * inv3, (a0.y + a1.y + a2.y) * inv3,
                      (a0.z + a1.z + a2.z) * inv3, (a0.w + a1.w + a2.w) * inv3 };
        const float* baseb = base + 512;
        float4 c0 = *(const float4*)baseb;
        float4 c1 = *(const float4*)(baseb + HW0);
        float4 c2 = *(const float4*)(baseb + 2 * HW0);
        float4 g1 = { (c0.x + c1.x + c2.x) * inv3, (c0.y + c1.y + c2.y) * inv3,
                      (c0.z + c1.z + c2.z) * inv3, (c0.w + c1.w + c2.w) * inv3 };
        float* L0 = &g_gray[img][(size_t)b * HW0 + (size_t)(s * 8 + 2 * r1) * 512 + 4 * k];
        *(float4*)L0         = g0;
        *(float4*)(L0 + 512) = g1;
        float2 l1 = { (g0.x + g0.y + g1.x + g1.y) * 0.25f,
                      (g0.z + g0.w + g1.z + g1.w) * 0.25f };
        *(float2*)&s1[img][r1][2 * k] = l1;
        *(float2*)&g_gray[img][OFF1 + (size_t)b * 256 * 256 + (size_t)(s * 4 + r1) * 256 + 2 * k] = l1;
    }
    __syncthreads();

    // L2
    for (int i = tid; i < 512; i += 256) {
        int img = i >> 8;
        int rem = i & 255;
        int r   = rem >> 7;
        int c   = rem & 127;
        float2 t0 = *(const float2*)&s1[img][2 * r][2 * c];
        float2 t1 = *(const float2*)&s1[img][2 * r + 1][2 * c];
        float v = (t0.x + t0.y + t1.x + t1.y) * 0.25f;
        s2[img][r][c] = v;
        g_gray[img][OFF2 + (size_t)b * 128 * 128 + (size_t)(s * 2 + r) * 128 + c] = v;
    }
    __syncthreads();

    // L3
    if (tid < 128) {
        int img = tid >> 6;
        int c   = tid & 63;
        float2 t0 = *(const float2*)&s2[img][0][2 * c];
        float2 t1 = *(const float2*)&s2[img][1][2 * c];
        float v = (t0.x + t0.y + t1.x + t1.y) * 0.25f;
        g_gray[img][OFF3 + (size_t)b * 64 * 64 + (size_t)s * 64 + c] = v;
    }
}

// ---------------------------------------------------------------------------
// Fused GMS tile. gray stride 48 (col cc = OX-4+cc, quads aligned), med
// stride 40; all quad accesses 16B-aligned LDS.128/STS.128.
// ---------------------------------------------------------------------------
struct Smem {
    float g[2][36][48];     // gray: row r = gray row OY-1+r
    float med[2][34][40];   // median-of-9 tile
    float wsum[8];
};

__device__ __forceinline__ float med3f(float a, float b, float c) {
    return fmaxf(fminf(a, b), fminf(fmaxf(a, b), c));
}
__device__ __forceinline__ void sort3f(float& a, float& b, float& c) {
    float t;
    t = fminf(a, b); b = fmaxf(a, b); a = t;
    t = fminf(b, c); c = fmaxf(b, c); b = t;
    t = fminf(a, b); b = fmaxf(a, b); a = t;
}

template <int H, int W, int LOGT>
__device__ __forceinline__ void gms_tile(Smem& sm, int local, int off, int gbid) {
    constexpr int T = 1 << LOGT;
    const int bx = local & (T - 1);
    const int by = (local >> LOGT) & (T - 1);
    const int b  = local >> (2 * LOGT);
    const int OX = bx * 32;
    const int OY = by * 32;
    const int tid = threadIdx.x;

    const float* __restrict__ g0 = &g_gray[0][off + (size_t)b * H * W];
    const float* __restrict__ g1 = &g_gray[1][off + (size_t)b * H * W];

    const bool interior = (OX >= 4) && (OX + 36 <= W) && (OY >= 1) && (OY + 35 <= H);

    // ---- Stage A: unified per-quad gray loads (2 img x 36 rows x 12 quads) ----
    for (int i = tid; i < 864; i += 256) {
        int img = (i >= 432);
        int rem = i - img * 432;
        int r   = rem / 12;
        int k   = rem - 12 * r;
        int gy  = OY - 1 + r;
        int gc  = OX - 4 + 4 * k;
        const float* g = img ? g1 : g0;
        float vv[4] = {0.f, 0.f, 0.f, 0.f};
        if ((unsigned)gy < (unsigned)H) {
            if (gc >= 0 && gc + 4 <= W) {
                *(float4*)vv = *(const float4*)(g + (size_t)gy * W + gc);
            } else {
#pragma unroll
                for (int j = 0; j < 4; j++) {
                    int x = gc + j;
                    if ((unsigned)x < (unsigned)W)
                        vv[j] = __ldg(g + (size_t)gy * W + x);
                }
            }
        }
        *(float4*)&sm.g[img][r][4 * k] = *(float4*)vv;
    }
    __syncthreads();

    // ---- Stage BC (fused): 4 medians/task from 6 LDS.128 + 3 LDS ----
    // Median (r, c0+m) uses vertical-sorted triples of gray cols c0+3+m..c0+5+m.
    for (int i = tid; i < 612; i += 256) {         // 2 img x 34 rows x 9 quads
        int img = i / 306;
        int rem = i - img * 306;
        int r   = rem / 9;
        int q   = rem - 9 * r;
        int c0  = 4 * q;
        float f[3][8], e[3];
#pragma unroll
        for (int rr = 0; rr < 3; rr++) {
            *(float4*)&f[rr][0] = *(const float4*)&sm.g[img][r + rr][c0];
            *(float4*)&f[rr][4] = *(const float4*)&sm.g[img][r + rr][c0 + 4];
            e[rr] = sm.g[img][r + rr][c0 + 8];
        }
        float lo[6], mi[6], hi[6];
#pragma unroll
        for (int j = 0; j < 6; j++) {              // triple at gray cc = c0+3+j
            float v0 = (j < 5) ? f[0][3 + j] : e[0];
            float v1 = (j < 5) ? f[1][3 + j] : e[1];
            float v2 = (j < 5) ? f[2][3 + j] : e[2];
            sort3f(v0, v1, v2);
            lo[j] = v0; mi[j] = v1; hi[j] = v2;
        }
        float out[4];
#pragma unroll
        for (int m = 0; m < 4; m++) {
            float L  = fmaxf(fmaxf(lo[m], lo[m + 1]), lo[m + 2]);
            float M  = med3f(mi[m], mi[m + 1], mi[m + 2]);
            float Hh = fminf(fminf(hi[m], hi[m + 1]), hi[m + 2]);
            out[m] = med3f(L, M, Hh);
        }
        *(float4*)&sm.med[img][r][c0] = *(float4*)&out[0];
    }
    __syncthreads();

    // ---- Stage D: Prewitt + GMS, 4 px/thread via 12 LDS.128 ----
    // gmap with unscaled gradients: (2*sqrt(tI*tR) + 9c)/(tI + tR + 9c)
    const float C9 = 9.0f * C_GMS;
    const int q   = tid & 7;          // col quad: output cols OX+4q..OX+4q+3
    const int row = tid >> 3;         // output row OY+row
    float t[2][4];
#pragma unroll
    for (int img = 0; img < 2; img++) {
        float r0[8], r1[8], r2[8];
        *(float4*)&r0[0] = *(const float4*)&sm.med[img][row][4 * q];
        *(float4*)&r0[4] = *(const float4*)&sm.med[img][row][4 * q + 4];
        *(float4*)&r1[0] = *(const float4*)&sm.med[img][row + 1][4 * q];
        *(float4*)&r1[4] = *(const float4*)&sm.med[img][row + 1][4 * q + 4];
        *(float4*)&r2[0] = *(const float4*)&sm.med[img][row + 2][4 * q];
        *(float4*)&r2[4] = *(const float4*)&sm.med[img][row + 2][4 * q + 4];
        float cs[6];
#pragma unroll
        for (int c = 0; c < 6; c++) cs[c] = r0[c] + r1[c] + r2[c];
#pragma unroll
        for (int j = 0; j < 4; j++) {
            float u = cs[j + 2] - cs[j];
            float v = (r0[j] + r0[j + 1] + r0[j + 2]) - (r2[j] + r2[j + 1] + r2[j + 2]);
            t[img][j] = u * u + v * v;
        }
    }
    float acc = 0.0f;
#pragma unroll
    for (int j = 0; j < 4; j++) {
        bool valid = interior || ((OY + row < H - 2) && (OX + 4 * q + j < W - 2));
        if (valid) {
            float p = t[0][j] * t[1][j];
            float s = p * rsqrtf(p + 1e-30f);      // sqrt(p), branchless, 0-safe
            float num = 2.0f * s + C9;
            float den = t[0][j] + t[1][j] + C9;
            acc += 1.0f - __fdividef(num, den);
        }
    }

    // ---- block reduction ----
#pragma unroll
    for (int o = 16; o > 0; o >>= 1) acc += __shfl_down_sync(0xffffffffu, acc, o);
    if ((tid & 31) == 0) sm.wsum[tid >> 5] = acc;
    __syncthreads();
    if (tid < 8) {
        float s = sm.wsum[tid];
#pragma unroll
        for (int o = 4; o > 0; o >>= 1) s += __shfl_down_sync(0xffu, s, o);
        if (tid == 0) {
            constexpr float wgt = 1.0f / (4.0f * (float)NB * (float)(H - 2) * (float)(W - 2));
            g_partial[gbid] = (double)(s * wgt);
        }
    }
}

__global__ __launch_bounds__(256) void gms_all_k() {
    __shared__ Smem sm;
    const int bid = blockIdx.x;
    if (bid < N0) {
        gms_tile<512, 512, 4>(sm, bid, OFF0, bid);
    } else if (bid < N0 + N1) {
        gms_tile<256, 256, 3>(sm, bid - N0, OFF1, bid);
    } else if (bid < N0 + N1 + N2) {
        gms_tile<128, 128, 2>(sm, bid - N0 - N1, OFF2, bid);
    } else {
        gms_tile<64, 64, 1>(sm, bid - N0 - N1 - N2, OFF3, bid);
    }
}

// ---------------------------------------------------------------------------
// Kernel 3: deterministic fixed-order reduction of per-block partials.
// ---------------------------------------------------------------------------
__global__ __launch_bounds__(256) void finalize_k(float* __restrict__ out) {
    __shared__ double ws[8];
    double s = 0.0;
    for (int i = threadIdx.x; i < NBLK; i += 256) s += g_partial[i];
#pragma unroll
    for (int o = 16; o > 0; o >>= 1) s += __shfl_down_sync(0xffffffffu, s, o);
    if ((threadIdx.x & 31) == 0) ws[threadIdx.x >> 5] = s;
    __syncthreads();
    if (threadIdx.x < 8) {
        double t = ws[threadIdx.x];
#pragma unroll
        for (int o = 4; o > 0; o >>= 1) t += __shfl_down_sync(0xffu, t, o);
        if (threadIdx.x == 0) out[0] = (float)t;
    }
}

// ---------------------------------------------------------------------------
extern "C" void kernel_launch(void* const* d_in, const int* in_sizes, int n_in,
                              void* d_out, int out_size) {
    const float* Ii = (const float*)d_in[0];
    const float* Ir = (const float*)d_in[1];
    float* out = (float*)d_out;

    graypyr_k<<<dim3(64, NB), 256>>>(Ii, Ir);
    gms_all_k<<<NBLK, 256>>>();
    finalize_k<<<1, 256>>>(out);
}